// round 15
// baseline (speedup 1.0000x reference)
#include <cuda_runtime.h>
#include <cuda_bf16.h>
#include <cstdint>

#define H 128
#define NB 8
#define NV 1024
#define NM 64

// ---------------------------------------------------------------------------
// Scratch (device globals — no allocation allowed)
// ---------------------------------------------------------------------------
__device__ float g_WeffV[H * H];
__device__ float g_beffV[H];
__device__ float g_WeffL[H * H];
__device__ float g_beffL[H];
__device__ float g_vp[NB * NV * H];     // v_part (folded)  [8192,128]
__device__ float g_lb[NB * NM * H];     // l_part + b1      [512,128]
// W2 fragments, k-PERMUTED layout: uint4[ks][jt][lane] = (bh0,bh1,bl0,bl1)
// slot b0 = phys k {16ks+4q, +1}, slot b1 = phys k {16ks+4q+2, +3}, col jt*8+g
__device__ uint4 g_W2f4[8 * 8 * 32];
__device__ float g_z[NB * NM * NV];     // pairwise logits [512,1024]

// ---------------------------------------------------------------------------
// Helpers
// ---------------------------------------------------------------------------
__device__ __forceinline__ uint32_t pack_bf16(__nv_bfloat16 lo_elem, __nv_bfloat16 hi_elem) {
    return (uint32_t)__bfloat16_as_ushort(lo_elem) |
           ((uint32_t)__bfloat16_as_ushort(hi_elem) << 16);
}
__device__ __forceinline__ void bf16_split(float x, __nv_bfloat16& hi, __nv_bfloat16& lo) {
    hi = __float2bfloat16(x);
    lo = __float2bfloat16(x - __bfloat162float(hi));
}
// bf16 tensor-core MMA (sm_80+ baseline). NON-volatile (CUTLASS-style):
// pure register op, lets NVVM interleave terms with loads/builds.
__device__ __forceinline__ void mma_bf16(float c[4], const uint32_t a[4], const uint2& b) {
    asm("mma.sync.aligned.m16n8k16.row.col.f32.bf16.bf16.f32 "
        "{%0,%1,%2,%3}, {%4,%5,%6,%7}, {%8,%9}, {%0,%1,%2,%3};"
        : "+f"(c[0]), "+f"(c[1]), "+f"(c[2]), "+f"(c[3])
        : "r"(a[0]), "r"(a[1]), "r"(a[2]), "r"(a[3]), "r"(b.x), "r"(b.y));
}
// relu(v+lb) over 2 cols -> packed bf16 hi + residual lo.
__device__ __forceinline__ void make_frag2(float vx, float vy, float lx, float ly,
                                           uint32_t& ah, uint32_t& al) {
    float x0 = fmaxf(vx + lx, 0.f);
    float x1 = fmaxf(vy + ly, 0.f);
    uint32_t h;
    asm("cvt.rn.bf16x2.f32 %0, %1, %2;" : "=r"(h) : "f"(x1), "f"(x0));
    float h0 = __uint_as_float(h << 16);
    float h1 = __uint_as_float(h & 0xffff0000u);
    float r0 = x0 - h0, r1 = x1 - h1;
    uint32_t l;
    asm("cvt.rn.bf16x2.f32 %0, %1, %2;" : "=r"(l) : "f"(r1), "f"(r0));
    ah = h; al = l;
}

// ---------------------------------------------------------------------------
// Kernel 1: fold Wv@W1[H:] and Wl@W1[:H] (+ biases) into single 128x128 mats.
// ---------------------------------------------------------------------------
__global__ void fold_kernel(const float* __restrict__ Wv, const float* __restrict__ bv,
                            const float* __restrict__ Wl, const float* __restrict__ bl,
                            const float* __restrict__ W1, const float* __restrict__ b1)
{
    int h = threadIdx.x;
    int row = blockIdx.x;      // 0..128
    int which = blockIdx.y;    // 0 = virtual, 1 = ligand
    const float* A;
    int w1off;
    if (which == 0) { A = (row < H) ? (Wv + row * H) : bv; w1off = H; }
    else            { A = (row < H) ? (Wl + row * H) : bl; w1off = 0; }
    float a0 = 0.f, a1 = 0.f, a2 = 0.f, a3 = 0.f;
#pragma unroll 8
    for (int hid = 0; hid < H; hid += 4) {
        a0 += A[hid + 0] * W1[(w1off + hid + 0) * H + h];
        a1 += A[hid + 1] * W1[(w1off + hid + 1) * H + h];
        a2 += A[hid + 2] * W1[(w1off + hid + 2) * H + h];
        a3 += A[hid + 3] * W1[(w1off + hid + 3) * H + h];
    }
    float acc = (a0 + a1) + (a2 + a3);
    if (row < H) {
        (which == 0 ? g_WeffV : g_WeffL)[row * H + h] = acc;
    } else {
        if (which == 1) acc += b1[h];
        (which == 0 ? g_beffV : g_beffL)[h] = acc;
    }
}

// ---------------------------------------------------------------------------
// Kernel 1b: W2 -> bf16 hi/lo fragments, k-permuted order matching the A-side
// float4 loads: b0 = phys k {16ks+4q,+1}, b1 = {16ks+4q+2,+3}.
// ---------------------------------------------------------------------------
__global__ void w2frag_kernel(const float* __restrict__ W2)
{
    int idx = blockIdx.x * blockDim.x + threadIdx.x;   // 0..2047
    int ks = (idx >> 8) & 7, jt = (idx >> 5) & 7, l = idx & 31;
    int q = l & 3, g = l >> 2;
    int j = jt * 8 + g;
    int k0 = ks * 16 + 4 * q;
    float w0 = W2[(k0 + 0) * 64 + j];
    float w1 = W2[(k0 + 1) * 64 + j];
    float w2 = W2[(k0 + 2) * 64 + j];
    float w3 = W2[(k0 + 3) * 64 + j];
    __nv_bfloat16 h0, l0, h1, l1, h2, l2, h3, l3;
    bf16_split(w0, h0, l0); bf16_split(w1, h1, l1);
    bf16_split(w2, h2, l2); bf16_split(w3, h3, l3);
    g_W2f4[idx] = make_uint4(pack_bf16(h0, h1), pack_bf16(h2, h3),
                             pack_bf16(l0, l1), pack_bf16(l2, l3));
}

// ---------------------------------------------------------------------------
// Kernel 2: projections — smem staging REMOVED. A-row addresses are warp-
// uniform (broadcast loads), W rows coalesced + L1-resident across CTAs;
// register-only kernel -> no smem occupancy cap.
// 256 threads, 32 rows/CTA, per-thread 4x4 tile.
// ---------------------------------------------------------------------------
__global__ void __launch_bounds__(256)
proj_kernel(const float* __restrict__ virt, const float* __restrict__ lig)
{
    int bid = blockIdx.x;
    const float *A, *W, *bias;
    float* C;
    if (bid < 256) { A = virt + bid * 32 * H; W = g_WeffV; bias = g_beffV; C = g_vp + bid * 32 * H; }
    else { int r = bid - 256; A = lig + r * 32 * H; W = g_WeffL; bias = g_beffL; C = g_lb + r * 32 * H; }

    int tid = threadIdx.x;
    int ct = tid & 31, rt = tid >> 5;

    float acc[4][4];
#pragma unroll
    for (int j = 0; j < 4; j++) {
        float bv = __ldg(bias + ct * 4 + j);
#pragma unroll
        for (int i = 0; i < 4; i++) acc[i][j] = bv;
    }

    const float* Arow = A + rt * 4 * H;
#pragma unroll 4
    for (int k = 0; k < H; k++) {
        float4 w = __ldg((const float4*)(W + k * H) + ct);
#pragma unroll
        for (int i = 0; i < 4; i++) {
            float a = __ldg(Arow + i * H + k);   // warp-uniform broadcast
            acc[i][0] += a * w.x; acc[i][1] += a * w.y;
            acc[i][2] += a * w.z; acc[i][3] += a * w.w;
        }
    }
#pragma unroll
    for (int i = 0; i < 4; i++)
        *(float4*)&C[(rt * 4 + i) * H + ct * 4] =
            make_float4(acc[i][0], acc[i][1], acc[i][2], acc[i][3]);
}

// ---------------------------------------------------------------------------
// Kernel 3 (pairz): R12 config (measured best): one CTA = 128 threads =
// 4 warps per (bm, t) tile, occ 3, resident uint4 B fragments. A fragments
// from one LDG.128 per row-quad per ks (k-permuted slots). No smem/barriers.
// ---------------------------------------------------------------------------
__global__ void __launch_bounds__(128, 3)
pairz_kernel(const float* __restrict__ b2, const float* __restrict__ W3)
{
    int tid = threadIdx.x;
    int wid = tid >> 5, lid = tid & 31;
    int q = lid & 3, g = lid >> 2;
    int bid = blockIdx.x;
    int bm = bid & 511;          // t-major: same-t CTAs adjacent (L1/L2 reuse)
    int t = bid >> 9;
    int b = bm >> 6;
    int n0 = t * 128;

    // row base in float4 units: row = n0 + wid*32 + g, lane col offset q f4s
    const float4* pr0 = (const float4*)(g_vp + (size_t)b * NV * H) +
                        (size_t)(n0 + wid * 32 + g) * (H / 4) + q;
    const float4* lb4 = (const float4*)(g_lb + (size_t)bm * H) + q;

    float c[2][8][4];
#pragma unroll
    for (int s = 0; s < 2; s++)
#pragma unroll
        for (int jt = 0; jt < 8; jt++)
#pragma unroll
            for (int e = 0; e < 4; e++) c[s][jt][e] = 0.f;

#pragma unroll
    for (int ks = 0; ks < 8; ks++) {
        float4 lbv = __ldg(lb4 + ks * 4);   // phys cols 16ks+4q .. +3

        // A fragments: slots a0/a2 <- row g float4; a1/a3 <- row g+8 float4
        uint32_t ah[2][4], al[2][4];
#pragma unroll
        for (int s = 0; s < 2; s++) {
            float4 f0 = __ldg(pr0 + s * 16 * (H / 4) + ks * 4);
            float4 f1 = __ldg(pr0 + (s * 16 + 8) * (H / 4) + ks * 4);
            make_frag2(f0.x, f0.y, lbv.x, lbv.y, ah[s][0], al[s][0]);
            make_frag2(f0.z, f0.w, lbv.z, lbv.w, ah[s][2], al[s][2]);
            make_frag2(f1.x, f1.y, lbv.x, lbv.y, ah[s][1], al[s][1]);
            make_frag2(f1.z, f1.w, lbv.z, lbv.w, ah[s][3], al[s][3]);
        }

        uint2 bh[8], bl[8];
#pragma unroll
        for (int jt = 0; jt < 8; jt++) {
            uint4 w = __ldg(g_W2f4 + ks * 256 + jt * 32 + lid);
            bh[jt] = make_uint2(w.x, w.y);
            bl[jt] = make_uint2(w.z, w.w);
        }

        // term-major 3-term split: 16 independent MMAs per term
#pragma unroll
        for (int s = 0; s < 2; s++)
#pragma unroll
            for (int jt = 0; jt < 8; jt++)
                mma_bf16(c[s][jt], ah[s], bh[jt]);
#pragma unroll
        for (int s = 0; s < 2; s++)
#pragma unroll
            for (int jt = 0; jt < 8; jt++)
                mma_bf16(c[s][jt], al[s], bh[jt]);
#pragma unroll
        for (int s = 0; s < 2; s++)
#pragma unroll
            for (int jt = 0; jt < 8; jt++)
                mma_bf16(c[s][jt], ah[s], bl[jt]);
    }

    // ---- epilogue: z = w3 . relu(c + b2); full sum in-warp, no atomics ----
    float* zrow = g_z + (size_t)bm * NV + n0 + wid * 32;
#pragma unroll
    for (int s = 0; s < 2; s++) {
        float z0 = 0.f, z1 = 0.f;
#pragma unroll
        for (int jt = 0; jt < 8; jt++) {
#pragma unroll
            for (int e = 0; e < 2; e++) {
                int j = jt * 8 + 2 * q + e;
                float bb = __ldg(b2 + j), ww = __ldg(W3 + j);
                z0 += fmaxf(c[s][jt][e] + bb, 0.f) * ww;
                z1 += fmaxf(c[s][jt][2 + e] + bb, 0.f) * ww;
            }
        }
        z0 += __shfl_xor_sync(0xffffffffu, z0, 1);
        z0 += __shfl_xor_sync(0xffffffffu, z0, 2);
        z1 += __shfl_xor_sync(0xffffffffu, z1, 1);
        z1 += __shfl_xor_sync(0xffffffffu, z1, 2);
        if (q == 0) {
            zrow[s * 16 + g] = z0;
            zrow[s * 16 + g + 8] = z1;
        }
    }
}

// ---------------------------------------------------------------------------
// Kernel 4 (softmax + coords): one CTA per bm. __expf (MUFU) — adds ~1e-6
// rel err, margin ~500x.
// ---------------------------------------------------------------------------
__global__ void __launch_bounds__(256)
soft_kernel(const float* __restrict__ vc, const int* __restrict__ mask,
            float* __restrict__ out)
{
    __shared__ float zs[1024];
    __shared__ float red[24];

    int tid = threadIdx.x;
    int wid = tid >> 5, lid = tid & 31;
    int bm = blockIdx.x;
    int b = bm >> 6;

    {
        const float4* src = (const float4*)(g_z + (size_t)bm * NV);
        float4 v = src[tid];
        *(float4*)&zs[tid * 4] = v;
    }
    __syncthreads();

    float mx = -3.4e38f;
    for (int n = tid; n < 1024; n += 256) mx = fmaxf(mx, zs[n]);
#pragma unroll
    for (int o = 16; o > 0; o >>= 1) mx = fmaxf(mx, __shfl_xor_sync(0xffffffffu, mx, o));
    if (lid == 0) red[wid] = mx;
    __syncthreads();
    mx = red[0];
#pragma unroll
    for (int j = 1; j < 8; j++) mx = fmaxf(mx, red[j]);

    float sum = 0.f;
    for (int n = tid; n < 1024; n += 256) {
        float e = __expf(zs[n] - mx);
        zs[n] = e;
        sum += e;
    }
#pragma unroll
    for (int o = 16; o > 0; o >>= 1) sum += __shfl_xor_sync(0xffffffffu, sum, o);
    __syncthreads();
    if (lid == 0) red[wid] = sum;
    __syncthreads();
    sum = 0.f;
#pragma unroll
    for (int j = 0; j < 8; j++) sum += red[j];
    float inv = 1.f / sum;
    float mk = mask[bm] ? 1.f : 0.f;

    float cx = 0.f, cy = 0.f, cz = 0.f;
    const float* vcB = vc + (size_t)b * NV * 3;
    float* attn_out = out + 1536 + (size_t)bm * 1024;
    for (int n = tid; n < 1024; n += 256) {
        float a = zs[n] * inv * mk;
        attn_out[n] = a;
        cx += a * vcB[n * 3 + 0];
        cy += a * vcB[n * 3 + 1];
        cz += a * vcB[n * 3 + 2];
    }
#pragma unroll
    for (int o = 16; o > 0; o >>= 1) {
        cx += __shfl_xor_sync(0xffffffffu, cx, o);
        cy += __shfl_xor_sync(0xffffffffu, cy, o);
        cz += __shfl_xor_sync(0xffffffffu, cz, o);
    }
    __syncthreads();
    if (lid == 0) { red[wid] = cx; red[8 + wid] = cy; red[16 + wid] = cz; }
    __syncthreads();
    if (tid == 0) {
        float X = 0, Y = 0, Z = 0;
#pragma unroll
        for (int j = 0; j < 8; j++) { X += red[j]; Y += red[8 + j]; Z += red[16 + j]; }
        out[bm * 3 + 0] = X;
        out[bm * 3 + 1] = Y;
        out[bm * 3 + 2] = Z;
    }
}

// ---------------------------------------------------------------------------
extern "C" void kernel_launch(void* const* d_in, const int* in_sizes, int n_in,
                              void* d_out, int out_size)
{
    const float* virt = (const float*)d_in[0];
    const float* vcoords = (const float*)d_in[1];
    const float* lig = (const float*)d_in[2];
    const int* mask = (const int*)d_in[5];   // bool stored as int32
    const float* Wv = (const float*)d_in[6];
    const float* bv = (const float*)d_in[7];
    const float* Wl = (const float*)d_in[8];
    const float* bl = (const float*)d_in[9];
    const float* W1 = (const float*)d_in[10];
    const float* b1 = (const float*)d_in[11];
    const float* W2 = (const float*)d_in[12];
    const float* b2 = (const float*)d_in[13];
    const float* W3 = (const float*)d_in[14];
    // d_in[15] = b3: softmax shift-invariant, unused.
    float* out = (float*)d_out;

    fold_kernel<<<dim3(129, 2), 128>>>(Wv, bv, Wl, bl, W1, b1);
    w2frag_kernel<<<8, 256>>>(W2);
    proj_kernel<<<272, 256>>>(virt, lig);
    pairz_kernel<<<4096, 128>>>(b2, W3);
    soft_kernel<<<512, 256>>>(vcoords, mask, out);
}

// round 16
// speedup vs baseline: 1.2439x; 1.2439x over previous
#include <cuda_runtime.h>
#include <cuda_bf16.h>
#include <cstdint>

#define H 128
#define NB 8
#define NV 1024
#define NM 64

// ---------------------------------------------------------------------------
// Scratch (device globals — no allocation allowed)
// ---------------------------------------------------------------------------
__device__ float g_WeffV[H * H];
__device__ float g_beffV[H];
__device__ float g_WeffL[H * H];
__device__ float g_beffL[H];
__device__ float g_vp[NB * NV * H];     // v_part (folded)  [8192,128]
__device__ float g_lb[NB * NM * H];     // l_part + b1      [512,128]
// W2 fragments, k-PERMUTED layout: uint4[ks][jt][lane] = (bh0,bh1,bl0,bl1)
// slot b0 = phys k {16ks+4q, +1}, slot b1 = phys k {16ks+4q+2, +3}, col jt*8+g
__device__ uint4 g_W2f4[8 * 8 * 32];
__device__ float g_z[NB * NM * NV];     // pairwise logits [512,1024]

// ---------------------------------------------------------------------------
// Helpers
// ---------------------------------------------------------------------------
__device__ __forceinline__ uint32_t pack_bf16(__nv_bfloat16 lo_elem, __nv_bfloat16 hi_elem) {
    return (uint32_t)__bfloat16_as_ushort(lo_elem) |
           ((uint32_t)__bfloat16_as_ushort(hi_elem) << 16);
}
__device__ __forceinline__ void bf16_split(float x, __nv_bfloat16& hi, __nv_bfloat16& lo) {
    hi = __float2bfloat16(x);
    lo = __float2bfloat16(x - __bfloat162float(hi));
}
// bf16 tensor-core MMA (sm_80+ baseline), non-volatile (measured neutral).
__device__ __forceinline__ void mma_bf16(float c[4], const uint32_t a[4], const uint2& b) {
    asm("mma.sync.aligned.m16n8k16.row.col.f32.bf16.bf16.f32 "
        "{%0,%1,%2,%3}, {%4,%5,%6,%7}, {%8,%9}, {%0,%1,%2,%3};"
        : "+f"(c[0]), "+f"(c[1]), "+f"(c[2]), "+f"(c[3])
        : "r"(a[0]), "r"(a[1]), "r"(a[2]), "r"(a[3]), "r"(b.x), "r"(b.y));
}
// relu(v+lb) over 2 cols -> packed bf16 hi + residual lo.
__device__ __forceinline__ void make_frag2(float vx, float vy, float lx, float ly,
                                           uint32_t& ah, uint32_t& al) {
    float x0 = fmaxf(vx + lx, 0.f);
    float x1 = fmaxf(vy + ly, 0.f);
    uint32_t h;
    asm("cvt.rn.bf16x2.f32 %0, %1, %2;" : "=r"(h) : "f"(x1), "f"(x0));
    float h0 = __uint_as_float(h << 16);
    float h1 = __uint_as_float(h & 0xffff0000u);
    float r0 = x0 - h0, r1 = x1 - h1;
    uint32_t l;
    asm("cvt.rn.bf16x2.f32 %0, %1, %2;" : "=r"(l) : "f"(r1), "f"(r0));
    ah = h; al = l;
}

// ---------------------------------------------------------------------------
// Kernel 1 (fused): fold (blockIdx.y 0/1) + w2frag (blockIdx.y 2).
// fold: split-k over 2 groups of 128 threads, smem reduce (halves the
// latency-bound serial FMA chain). w2frag: first 16 x-blocks do W2 split.
// ---------------------------------------------------------------------------
__global__ void prep_kernel(const float* __restrict__ Wv, const float* __restrict__ bv,
                            const float* __restrict__ Wl, const float* __restrict__ bl,
                            const float* __restrict__ W1, const float* __restrict__ b1,
                            const float* __restrict__ W2)
{
    int which = blockIdx.y;    // 0 = virtual-fold, 1 = ligand-fold, 2 = w2frag
    int tid = threadIdx.x;     // 0..255

    if (which == 2) {
        int idx = blockIdx.x * 16 + (tid >> 4);       // need 0..2047 -> use 128 x-blocks? no:
        // grid.x = 129; use first 8 blocks x 256 threads = 2048 work items
        idx = blockIdx.x * 256 + tid;
        if (idx < 2048) {
            int ks = (idx >> 8) & 7, jt = (idx >> 5) & 7, l = idx & 31;
            int q = l & 3, g = l >> 2;
            int j = jt * 8 + g;
            int k0 = ks * 16 + 4 * q;
            float w0 = W2[(k0 + 0) * 64 + j];
            float w1 = W2[(k0 + 1) * 64 + j];
            float w2 = W2[(k0 + 2) * 64 + j];
            float w3 = W2[(k0 + 3) * 64 + j];
            __nv_bfloat16 h0, l0, h1, l1, h2, l2, h3, l3;
            bf16_split(w0, h0, l0); bf16_split(w1, h1, l1);
            bf16_split(w2, h2, l2); bf16_split(w3, h3, l3);
            g_W2f4[idx] = make_uint4(pack_bf16(h0, h1), pack_bf16(h2, h3),
                                     pack_bf16(l0, l1), pack_bf16(l2, l3));
        }
        return;
    }

    __shared__ float part[128];
    int h = tid & 127;
    int kh = tid >> 7;           // k-half: 0 or 1
    int row = blockIdx.x;        // 0..128
    const float* A;
    int w1off;
    if (which == 0) { A = (row < H) ? (Wv + row * H) : bv; w1off = H; }
    else            { A = (row < H) ? (Wl + row * H) : bl; w1off = 0; }

    int kb = kh * 64;
    float a0 = 0.f, a1 = 0.f, a2 = 0.f, a3 = 0.f;
#pragma unroll 4
    for (int hid = 0; hid < 64; hid += 4) {
        a0 += A[kb + hid + 0] * W1[(w1off + kb + hid + 0) * H + h];
        a1 += A[kb + hid + 1] * W1[(w1off + kb + hid + 1) * H + h];
        a2 += A[kb + hid + 2] * W1[(w1off + kb + hid + 2) * H + h];
        a3 += A[kb + hid + 3] * W1[(w1off + kb + hid + 3) * H + h];
    }
    float acc = (a0 + a1) + (a2 + a3);
    if (kh == 1) part[h] = acc;
    __syncthreads();
    if (kh == 0) {
        acc += part[h];
        if (row < H) {
            (which == 0 ? g_WeffV : g_WeffL)[row * H + h] = acc;
        } else {
            if (which == 1) acc += b1[h];
            (which == 0 ? g_beffV : g_beffL)[h] = acc;
        }
    }
}

// ---------------------------------------------------------------------------
// Kernel 2: projections (known-good R12 smem version).
// ---------------------------------------------------------------------------
__global__ void proj_kernel(const float* __restrict__ virt, const float* __restrict__ lig)
{
    extern __shared__ float sm[];
    float* Ws = sm;
    float* As = Ws + H * H;
    float* bs = As + 32 * H;

    int bid = blockIdx.x;
    const float *A, *W, *bias;
    float* C;
    if (bid < 256) { A = virt + bid * 32 * H; W = g_WeffV; bias = g_beffV; C = g_vp + bid * 32 * H; }
    else { int r = bid - 256; A = lig + r * 32 * H; W = g_WeffL; bias = g_beffL; C = g_lb + r * 32 * H; }

    int tid = threadIdx.x;
    for (int i = tid; i < H * H / 4; i += 256)
        ((float4*)Ws)[i] = ((const float4*)W)[i];
    for (int i = tid; i < 32 * H / 4; i += 256)
        ((float4*)As)[i] = ((const float4*)A)[i];
    if (tid < H) bs[tid] = bias[tid];
    __syncthreads();

    int ct = tid & 31, rt = tid >> 5;
    float acc[4][4];
#pragma unroll
    for (int i = 0; i < 4; i++)
#pragma unroll
        for (int j = 0; j < 4; j++) acc[i][j] = bs[ct * 4 + j];

#pragma unroll 4
    for (int k = 0; k < H; k++) {
        float4 w = *(float4*)&Ws[k * H + ct * 4];
#pragma unroll
        for (int i = 0; i < 4; i++) {
            float a = As[(rt * 4 + i) * H + k];
            acc[i][0] += a * w.x; acc[i][1] += a * w.y;
            acc[i][2] += a * w.z; acc[i][3] += a * w.w;
        }
    }
#pragma unroll
    for (int i = 0; i < 4; i++)
        *(float4*)&C[(rt * 4 + i) * H + ct * 4] =
            make_float4(acc[i][0], acc[i][1], acc[i][2], acc[i][3]);
}

// ---------------------------------------------------------------------------
// Kernel 3 (pairz): R12 measured-best config: 128 threads / 4 warps per
// (bm, t) tile, occ 3, resident uint4 B fragments, k-permuted A LDG.128.
// No smem, no barriers, no atomics.
// ---------------------------------------------------------------------------
__global__ void __launch_bounds__(128, 3)
pairz_kernel(const float* __restrict__ b2, const float* __restrict__ W3)
{
    int tid = threadIdx.x;
    int wid = tid >> 5, lid = tid & 31;
    int q = lid & 3, g = lid >> 2;
    int bid = blockIdx.x;
    int bm = bid & 511;          // t-major: same-t CTAs adjacent (L1/L2 reuse)
    int t = bid >> 9;
    int b = bm >> 6;
    int n0 = t * 128;

    const float4* pr0 = (const float4*)(g_vp + (size_t)b * NV * H) +
                        (size_t)(n0 + wid * 32 + g) * (H / 4) + q;
    const float4* lb4 = (const float4*)(g_lb + (size_t)bm * H) + q;

    float c[2][8][4];
#pragma unroll
    for (int s = 0; s < 2; s++)
#pragma unroll
        for (int jt = 0; jt < 8; jt++)
#pragma unroll
            for (int e = 0; e < 4; e++) c[s][jt][e] = 0.f;

#pragma unroll
    for (int ks = 0; ks < 8; ks++) {
        float4 lbv = __ldg(lb4 + ks * 4);   // phys cols 16ks+4q .. +3

        uint32_t ah[2][4], al[2][4];
#pragma unroll
        for (int s = 0; s < 2; s++) {
            float4 f0 = __ldg(pr0 + s * 16 * (H / 4) + ks * 4);
            float4 f1 = __ldg(pr0 + (s * 16 + 8) * (H / 4) + ks * 4);
            make_frag2(f0.x, f0.y, lbv.x, lbv.y, ah[s][0], al[s][0]);
            make_frag2(f0.z, f0.w, lbv.z, lbv.w, ah[s][2], al[s][2]);
            make_frag2(f1.x, f1.y, lbv.x, lbv.y, ah[s][1], al[s][1]);
            make_frag2(f1.z, f1.w, lbv.z, lbv.w, ah[s][3], al[s][3]);
        }

        uint2 bh[8], bl[8];
#pragma unroll
        for (int jt = 0; jt < 8; jt++) {
            uint4 w = __ldg(g_W2f4 + ks * 256 + jt * 32 + lid);
            bh[jt] = make_uint2(w.x, w.y);
            bl[jt] = make_uint2(w.z, w.w);
        }

        // term-major 3-term split: 16 independent MMAs per term
#pragma unroll
        for (int s = 0; s < 2; s++)
#pragma unroll
            for (int jt = 0; jt < 8; jt++)
                mma_bf16(c[s][jt], ah[s], bh[jt]);
#pragma unroll
        for (int s = 0; s < 2; s++)
#pragma unroll
            for (int jt = 0; jt < 8; jt++)
                mma_bf16(c[s][jt], al[s], bh[jt]);
#pragma unroll
        for (int s = 0; s < 2; s++)
#pragma unroll
            for (int jt = 0; jt < 8; jt++)
                mma_bf16(c[s][jt], ah[s], bl[jt]);
    }

    // ---- epilogue: z = w3 . relu(c + b2); full sum in-warp, no atomics ----
    float* zrow = g_z + (size_t)bm * NV + n0 + wid * 32;
#pragma unroll
    for (int s = 0; s < 2; s++) {
        float z0 = 0.f, z1 = 0.f;
#pragma unroll
        for (int jt = 0; jt < 8; jt++) {
#pragma unroll
            for (int e = 0; e < 2; e++) {
                int j = jt * 8 + 2 * q + e;
                float bb = __ldg(b2 + j), ww = __ldg(W3 + j);
                z0 += fmaxf(c[s][jt][e] + bb, 0.f) * ww;
                z1 += fmaxf(c[s][jt][2 + e] + bb, 0.f) * ww;
            }
        }
        z0 += __shfl_xor_sync(0xffffffffu, z0, 1);
        z0 += __shfl_xor_sync(0xffffffffu, z0, 2);
        z1 += __shfl_xor_sync(0xffffffffu, z1, 1);
        z1 += __shfl_xor_sync(0xffffffffu, z1, 2);
        if (q == 0) {
            zrow[s * 16 + g] = z0;
            zrow[s * 16 + g + 8] = z1;
        }
    }
}

// ---------------------------------------------------------------------------
// Kernel 4 (softmax + coords): one CTA per bm. __expf (measured safe).
// ---------------------------------------------------------------------------
__global__ void __launch_bounds__(256)
soft_kernel(const float* __restrict__ vc, const int* __restrict__ mask,
            float* __restrict__ out)
{
    __shared__ float zs[1024];
    __shared__ float red[24];

    int tid = threadIdx.x;
    int wid = tid >> 5, lid = tid & 31;
    int bm = blockIdx.x;
    int b = bm >> 6;

    {
        const float4* src = (const float4*)(g_z + (size_t)bm * NV);
        float4 v = src[tid];
        *(float4*)&zs[tid * 4] = v;
    }
    __syncthreads();

    float mx = -3.4e38f;
    for (int n = tid; n < 1024; n += 256) mx = fmaxf(mx, zs[n]);
#pragma unroll
    for (int o = 16; o > 0; o >>= 1) mx = fmaxf(mx, __shfl_xor_sync(0xffffffffu, mx, o));
    if (lid == 0) red[wid] = mx;
    __syncthreads();
    mx = red[0];
#pragma unroll
    for (int j = 1; j < 8; j++) mx = fmaxf(mx, red[j]);

    float sum = 0.f;
    for (int n = tid; n < 1024; n += 256) {
        float e = __expf(zs[n] - mx);
        zs[n] = e;
        sum += e;
    }
#pragma unroll
    for (int o = 16; o > 0; o >>= 1) sum += __shfl_xor_sync(0xffffffffu, sum, o);
    __syncthreads();
    if (lid == 0) red[wid] = sum;
    __syncthreads();
    sum = 0.f;
#pragma unroll
    for (int j = 0; j < 8; j++) sum += red[j];
    float inv = 1.f / sum;
    float mk = mask[bm] ? 1.f : 0.f;

    float cx = 0.f, cy = 0.f, cz = 0.f;
    const float* vcB = vc + (size_t)b * NV * 3;
    float* attn_out = out + 1536 + (size_t)bm * 1024;
    for (int n = tid; n < 1024; n += 256) {
        float a = zs[n] * inv * mk;
        attn_out[n] = a;
        cx += a * vcB[n * 3 + 0];
        cy += a * vcB[n * 3 + 1];
        cz += a * vcB[n * 3 + 2];
    }
#pragma unroll
    for (int o = 16; o > 0; o >>= 1) {
        cx += __shfl_xor_sync(0xffffffffu, cx, o);
        cy += __shfl_xor_sync(0xffffffffu, cy, o);
        cz += __shfl_xor_sync(0xffffffffu, cz, o);
    }
    __syncthreads();
    if (lid == 0) { red[wid] = cx; red[8 + wid] = cy; red[16 + wid] = cz; }
    __syncthreads();
    if (tid == 0) {
        float X = 0, Y = 0, Z = 0;
#pragma unroll
        for (int j = 0; j < 8; j++) { X += red[j]; Y += red[8 + j]; Z += red[16 + j]; }
        out[bm * 3 + 0] = X;
        out[bm * 3 + 1] = Y;
        out[bm * 3 + 2] = Z;
    }
}

// ---------------------------------------------------------------------------
extern "C" void kernel_launch(void* const* d_in, const int* in_sizes, int n_in,
                              void* d_out, int out_size)
{
    const float* virt = (const float*)d_in[0];
    const float* vcoords = (const float*)d_in[1];
    const float* lig = (const float*)d_in[2];
    const int* mask = (const int*)d_in[5];   // bool stored as int32
    const float* Wv = (const float*)d_in[6];
    const float* bv = (const float*)d_in[7];
    const float* Wl = (const float*)d_in[8];
    const float* bl = (const float*)d_in[9];
    const float* W1 = (const float*)d_in[10];
    const float* b1 = (const float*)d_in[11];
    const float* W2 = (const float*)d_in[12];
    const float* b2 = (const float*)d_in[13];
    const float* W3 = (const float*)d_in[14];
    // d_in[15] = b3: softmax shift-invariant, unused.
    float* out = (float*)d_out;

    size_t smem2 = (size_t)(H * H + 32 * H + H) * sizeof(float);
    cudaFuncSetAttribute(proj_kernel, cudaFuncAttributeMaxDynamicSharedMemorySize, (int)smem2);

    prep_kernel<<<dim3(129, 3), 256>>>(Wv, bv, Wl, bl, W1, b1, W2);
    proj_kernel<<<272, 256, smem2>>>(virt, lig);
    pairz_kernel<<<4096, 128>>>(b2, W3);
    soft_kernel<<<512, 256>>>(vcoords, mask, out);
}